// round 14
// baseline (speedup 1.0000x reference)
#include <cuda_runtime.h>
#include <cuda_bf16.h>
#include <cstdint>

#define D_MODEL 1024
#define N_HEADS 16
#define DEPTH   64
#define BATCH   2
#define SEQ     2048
#define ROWS    (BATCH*SEQ)
#define NELEMS  (ROWS*D_MODEL)
#define DD      (D_MODEL*D_MODEL)

// ---------------- scratch (device globals; no allocations) ----------------
__device__ __nv_bfloat16 g_sph [3 * NELEMS];   // split inputs (q,k,v) hi
__device__ __nv_bfloat16 g_spl [3 * NELEMS];   // split inputs lo
__device__ __nv_bfloat16 g_wh  [4 * DD];       // weights^T hi (wq,wk,wv,wo)
__device__ __nv_bfloat16 g_wl  [4 * DD];       // weights^T lo
__device__ __nv_bfloat16 g_qkvh[3 * NELEMS];   // projected Q,K,V hi
__device__ __nv_bfloat16 g_qkvl[3 * NELEMS];   // projected Q,K,V lo
__device__ __nv_bfloat16 g_aoh [NELEMS];       // attention out hi
__device__ __nv_bfloat16 g_aol [NELEMS];       // attention out lo

// ---------------- helpers ----------------
__device__ __forceinline__ uint32_t smem_u32(const void* p) {
    uint32_t a;
    asm("{ .reg .u64 t; cvta.to.shared.u64 t, %1; cvt.u32.u64 %0, t; }"
        : "=r"(a) : "l"(p));
    return a;
}
__device__ __forceinline__ void mma16816(float* d, const uint32_t* a,
                                         uint32_t b0, uint32_t b1) {
    asm volatile(
        "mma.sync.aligned.m16n8k16.row.col.f32.bf16.bf16.f32 "
        "{%0,%1,%2,%3}, {%4,%5,%6,%7}, {%8,%9}, {%0,%1,%2,%3};"
        : "+f"(d[0]), "+f"(d[1]), "+f"(d[2]), "+f"(d[3])
        : "r"(a[0]), "r"(a[1]), "r"(a[2]), "r"(a[3]), "r"(b0), "r"(b1));
}
#define LDMX4(r0, r1, r2, r3, addr) \
    asm volatile("ldmatrix.sync.aligned.m8n8.x4.shared.b16 {%0,%1,%2,%3}, [%4];" \
                 : "=r"(r0), "=r"(r1), "=r"(r2), "=r"(r3) : "r"(addr))
#define LDMX4T(r0, r1, r2, r3, addr) \
    asm volatile("ldmatrix.sync.aligned.m8n8.x4.trans.shared.b16 {%0,%1,%2,%3}, [%4];" \
                 : "=r"(r0), "=r"(r1), "=r"(r2), "=r"(r3) : "r"(addr))
#define CPASYNC16(smaddr, gptr) \
    asm volatile("cp.async.cg.shared.global [%0], [%1], 16;" \
                 :: "r"(smaddr), "l"(gptr) : "memory")
#define CPCOMMIT()  asm volatile("cp.async.commit_group;" ::: "memory")
#define CPWAIT(n)   asm volatile("cp.async.wait_group %0;" :: "n"(n) : "memory")

// ---------------------------------------------------------------------------
// Batched split: fp32 -> (bf16 hi, bf16 lo).  blockIdx.y selects input 0..2.
// ---------------------------------------------------------------------------
__global__ __launch_bounds__(256) void split3_kernel(
    const float* __restrict__ in0, const float* __restrict__ in1,
    const float* __restrict__ in2,
    __nv_bfloat16* __restrict__ hi, __nv_bfloat16* __restrict__ lo)
{
    const int z = blockIdx.y;
    const float* in = (z == 0) ? in0 : (z == 1) ? in1 : in2;
    int i = (blockIdx.x * 256 + threadIdx.x) * 4;
    if (i >= NELEMS) return;
    float4 v = *(const float4*)(in + i);
    union { __nv_bfloat16 b[4]; uint2 u; } H, L;
    float f[4] = {v.x, v.y, v.z, v.w};
    #pragma unroll
    for (int j = 0; j < 4; j++) {
        H.b[j] = __float2bfloat16_rn(f[j]);
        L.b[j] = __float2bfloat16_rn(f[j] - __bfloat162float(H.b[j]));
    }
    size_t o = (size_t)z * NELEMS + i;
    *(uint2*)(hi + o) = H.u;
    *(uint2*)(lo + o) = L.u;
}

// ---------------------------------------------------------------------------
// Batched transpose+split: W[K][N] fp32 -> Wt hi/lo [N][K] bf16. z = 0..3.
// ---------------------------------------------------------------------------
__global__ __launch_bounds__(256) void split_t4_kernel(
    const float* __restrict__ W0, const float* __restrict__ W1,
    const float* __restrict__ W2, const float* __restrict__ W3,
    __nv_bfloat16* __restrict__ th, __nv_bfloat16* __restrict__ tl)
{
    __shared__ float tile[32][33];
    const int z = blockIdx.z;
    const float* W = (z == 0) ? W0 : (z == 1) ? W1 : (z == 2) ? W2 : W3;
    const size_t zoff = (size_t)z * DD;
    int x  = blockIdx.x * 32 + threadIdx.x;
    int y0 = blockIdx.y * 32;
    #pragma unroll
    for (int i = 0; i < 32; i += 8)
        tile[threadIdx.y + i][threadIdx.x] = W[(size_t)(y0 + threadIdx.y + i) * D_MODEL + x];
    __syncthreads();
    int k = y0 + threadIdx.x;
    #pragma unroll
    for (int i = 0; i < 32; i += 8) {
        int nn = blockIdx.x * 32 + threadIdx.y + i;
        float v = tile[threadIdx.x][threadIdx.y + i];
        __nv_bfloat16 h = __float2bfloat16_rn(v);
        th[zoff + (size_t)nn * D_MODEL + k] = h;
        tl[zoff + (size_t)nn * D_MODEL + k] = __float2bfloat16_rn(v - __bfloat162float(h));
    }
}

// ---------------------------------------------------------------------------
// bf16x2-split GEMM (proven core), batched over blockIdx.z.
// ---------------------------------------------------------------------------
#define SA 40
#define MATB   (128 * SA * 2)
#define STAGEB (4 * MATB)
#define GSMEM  (2 * STAGEB)

template<bool SPLIT_OUT>
__global__ __launch_bounds__(256, 2) void gemm_mma(
    const __nv_bfloat16* __restrict__ Ah0, const __nv_bfloat16* __restrict__ Al0,
    const __nv_bfloat16* __restrict__ Bh0, const __nv_bfloat16* __restrict__ Bl0,
    const float* __restrict__ b0, const float* __restrict__ b1,
    const float* __restrict__ b2,
    float* __restrict__ Cf,
    __nv_bfloat16* __restrict__ Ch0, __nv_bfloat16* __restrict__ Cl0)
{
    extern __shared__ char smem[];
    const uint32_t sb = smem_u32(smem);

    const int z = blockIdx.z;
    const __nv_bfloat16* Ah = Ah0 + (size_t)z * NELEMS;
    const __nv_bfloat16* Al = Al0 + (size_t)z * NELEMS;
    const __nv_bfloat16* Bh = Bh0 + (size_t)z * DD;
    const __nv_bfloat16* Bl = Bl0 + (size_t)z * DD;
    const float* bias = (z == 0) ? b0 : (z == 1) ? b1 : b2;
    __nv_bfloat16* Ch = Ch0 + (size_t)z * NELEMS;
    __nv_bfloat16* Cl = Cl0 + (size_t)z * NELEMS;

    const int tid  = threadIdx.x;
    const int wid  = tid >> 5, lane = tid & 31;
    const int wm   = wid & 3;
    const int wn   = wid >> 2;
    const int m0   = blockIdx.y * 128, n0 = blockIdx.x * 128;
    const int lg   = lane >> 2;
    const int lk   = (lane & 3) * 2;
    const int g8 = lane >> 3;
    const int r8 = lane & 7;

    float acc[2][8][4];
    #pragma unroll
    for (int mt = 0; mt < 2; mt++)
        #pragma unroll
        for (int nt = 0; nt < 8; nt++)
            #pragma unroll
            for (int r = 0; r < 4; r++) acc[mt][nt][r] = 0.f;

    auto load_stage = [&](int st, int k0) {
        const uint32_t s = sb + st * STAGEB;
        #pragma unroll
        for (int i = 0; i < 2; i++) {
            int idx = tid + i * 256;
            int r   = idx >> 2;
            int c16 = idx & 3;
            uint32_t so = (uint32_t)(r * (SA * 2) + c16 * 16);
            size_t ga = (size_t)(m0 + r) * D_MODEL + k0 + c16 * 8;
            size_t gb = (size_t)(n0 + r) * D_MODEL + k0 + c16 * 8;
            CPASYNC16(s + 0 * MATB + so, Ah + ga);
            CPASYNC16(s + 1 * MATB + so, Al + ga);
            CPASYNC16(s + 2 * MATB + so, Bh + gb);
            CPASYNC16(s + 3 * MATB + so, Bl + gb);
        }
    };

    load_stage(0, 0);
    CPCOMMIT();

    const int NIT = D_MODEL / 32;
    for (int it = 0; it < NIT; it++) {
        if (it + 1 < NIT) {
            load_stage((it + 1) & 1, (it + 1) * 32);
            CPCOMMIT();
            CPWAIT(1);
        } else {
            CPWAIT(0);
        }
        __syncthreads();

        const uint32_t s   = sb + (it & 1) * STAGEB;
        const uint32_t sAh = s;
        const uint32_t sAl = s + MATB;
        const uint32_t sBh = s + 2 * MATB;
        const uint32_t sBl = s + 3 * MATB;

        #pragma unroll
        for (int kk = 0; kk < 32; kk += 16) {
            uint32_t ah[2][4], al[2][4];
            #pragma unroll
            for (int mt = 0; mt < 2; mt++) {
                int row = wm * 32 + mt * 16 + (g8 & 1) * 8 + r8;
                int col = kk + (g8 >> 1) * 8;
                uint32_t off = (uint32_t)(row * (SA * 2) + col * 2);
                LDMX4(ah[mt][0], ah[mt][1], ah[mt][2], ah[mt][3], sAh + off);
                LDMX4(al[mt][0], al[mt][1], al[mt][2], al[mt][3], sAl + off);
            }
            #pragma unroll
            for (int np = 0; np < 4; np++) {
                int row = wn * 64 + np * 16 + (g8 >> 1) * 8 + r8;
                int col = kk + (g8 & 1) * 8;
                uint32_t off = (uint32_t)(row * (SA * 2) + col * 2);
                uint32_t bh0, bh1, bh2, bh3, bl0, bl1, bl2, bl3;
                LDMX4(bh0, bh1, bh2, bh3, sBh + off);
                LDMX4(bl0, bl1, bl2, bl3, sBl + off);
                #pragma unroll
                for (int mt = 0; mt < 2; mt++) {
                    mma16816(acc[mt][2 * np],     ah[mt], bh0, bh1);
                    mma16816(acc[mt][2 * np],     ah[mt], bl0, bl1);
                    mma16816(acc[mt][2 * np],     al[mt], bh0, bh1);
                    mma16816(acc[mt][2 * np + 1], ah[mt], bh2, bh3);
                    mma16816(acc[mt][2 * np + 1], ah[mt], bl2, bl3);
                    mma16816(acc[mt][2 * np + 1], al[mt], bh2, bh3);
                }
            }
        }
        __syncthreads();
    }

    #pragma unroll
    for (int mt = 0; mt < 2; mt++) {
        #pragma unroll
        for (int nt = 0; nt < 8; nt++) {
            int row = m0 + wm * 32 + mt * 16 + lg;
            int col = n0 + wn * 64 + nt * 8 + lk;
            float2 bb = *(const float2*)&bias[col];
            float v00 = acc[mt][nt][0] + bb.x, v01 = acc[mt][nt][1] + bb.y;
            float v10 = acc[mt][nt][2] + bb.x, v11 = acc[mt][nt][3] + bb.y;
            if (SPLIT_OUT) {
                __nv_bfloat162 h0 = __floats2bfloat162_rn(v00, v01);
                __nv_bfloat162 l0 = __floats2bfloat162_rn(
                    v00 - __bfloat162float(h0.x), v01 - __bfloat162float(h0.y));
                __nv_bfloat162 h1 = __floats2bfloat162_rn(v10, v11);
                __nv_bfloat162 l1 = __floats2bfloat162_rn(
                    v10 - __bfloat162float(h1.x), v11 - __bfloat162float(h1.y));
                *(__nv_bfloat162*)&Ch[(size_t)row * D_MODEL + col] = h0;
                *(__nv_bfloat162*)&Cl[(size_t)row * D_MODEL + col] = l0;
                *(__nv_bfloat162*)&Ch[(size_t)(row + 8) * D_MODEL + col] = h1;
                *(__nv_bfloat162*)&Cl[(size_t)(row + 8) * D_MODEL + col] = l1;
            } else {
                float2 o0 = {v00, v01}, o1 = {v10, v11};
                *(float2*)&Cf[(size_t)row * D_MODEL + col] = o0;
                *(float2*)&Cf[(size_t)(row + 8) * D_MODEL + col] = o1;
            }
        }
    }
}

// ---------------------------------------------------------------------------
// Flash-attention via mma.sync bf16 split precision (causal, UNSCALED).
// 64-key KV stages; Q frags reloaded from smem (low regs) -> 2 CTAs/SM.
// ---------------------------------------------------------------------------
#define SK   72
#define SKB  (SK * 2)                    // 144 B row stride
#define AQ_BYTES  (128 * SKB)            // 18432 per Q matrix
#define AKV_MAT   (64 * SKB)             // 9216 per K/V matrix (64 keys)
#define AKV_STAGE (4 * AKV_MAT)          // 36864
#define ASMEM (2 * AQ_BYTES + 2 * AKV_STAGE)   // 110592

__global__ __launch_bounds__(256, 2) void attn_mma(
    const __nv_bfloat16* __restrict__ qkvh, const __nv_bfloat16* __restrict__ qkvl,
    __nv_bfloat16* __restrict__ AOh, __nv_bfloat16* __restrict__ AOl)
{
    extern __shared__ char smem[];
    const uint32_t sb = smem_u32(smem);
    const uint32_t sQh = sb, sQl = sb + AQ_BYTES;
    const uint32_t sKV = sb + 2 * AQ_BYTES;

    const __nv_bfloat16* Qh = qkvh;
    const __nv_bfloat16* Ql = qkvl;
    const __nv_bfloat16* Kh = qkvh + (size_t)NELEMS;
    const __nv_bfloat16* Kl = qkvl + (size_t)NELEMS;
    const __nv_bfloat16* Vh = qkvh + 2 * (size_t)NELEMS;
    const __nv_bfloat16* Vl = qkvl + 2 * (size_t)NELEMS;

    const int qt = (gridDim.x - 1) - blockIdx.x;   // long CTAs first
    const int h  = blockIdx.y;
    const int b  = blockIdx.z;
    const int tid = threadIdx.x;
    const int wid = tid >> 5, lane = tid & 31;
    const int lg = lane >> 2, lk = (lane & 3) * 2;
    const int g8 = lane >> 3, r8 = lane & 7;

    const int q0 = qt * 128;
    const size_t gbase = ((size_t)b * SEQ) * D_MODEL + h * DEPTH;

    // ---- Q loads (hi+lo) into smem ----
    #pragma unroll
    for (int i = 0; i < 4; i++) {
        int idx = tid + i * 256;
        int r = idx >> 3, c = idx & 7;
        uint32_t so = (uint32_t)(r * SKB + c * 16);
        size_t g = gbase + (size_t)(q0 + r) * D_MODEL + c * 8;
        CPASYNC16(sQh + so, Qh + g);
        CPASYNC16(sQl + so, Ql + g);
    }

    auto load_kv = [&](int st, int kt) {
        const uint32_t s = sKV + st * AKV_STAGE;
        const int k0 = kt * 64;
        #pragma unroll
        for (int i = 0; i < 8; i++) {
            int idx = tid + i * 256;
            int arr = idx >> 9;
            int r = (idx >> 3) & 63, c = idx & 7;
            uint32_t so = s + arr * AKV_MAT + (uint32_t)(r * SKB + c * 16);
            size_t g = gbase + (size_t)(k0 + r) * D_MODEL + c * 8;
            const __nv_bfloat16* src = (arr == 0) ? Kh : (arr == 1) ? Kl
                                      : (arr == 2) ? Vh : Vl;
            CPASYNC16(so, src + g);
        }
    };

    load_kv(0, 0);
    CPCOMMIT();

    float m[2] = {-1e30f, -1e30f}, l[2] = {0.f, 0.f};
    float oacc[8][4];
    #pragma unroll
    for (int nt = 0; nt < 8; nt++)
        #pragma unroll
        for (int r = 0; r < 4; r++) oacc[nt][r] = 0.f;

    const int last = 2 * qt + 1;
    for (int kt = 0; kt <= last; kt++) {
        if (kt < last) {
            load_kv((kt + 1) & 1, kt + 1);
            CPCOMMIT();
            CPWAIT(1);
        } else {
            CPWAIT(0);
        }
        __syncthreads();

        // Fully-masked (diagonal upper half) tile for warps 0-3: skip compute.
        const bool skip = (kt == last) && (wid < 4);
        if (!skip) {
            const uint32_t s = sKV + (kt & 1) * AKV_STAGE;
            const uint32_t sKh = s, sKl = s + AKV_MAT;
            const uint32_t sVh = s + 2 * AKV_MAT, sVl = s + 3 * AKV_MAT;

            // ---- S = Q @ K^T (split; Q frags reloaded per k-slab) ----
            float sacc[8][4];
            #pragma unroll
            for (int nt = 0; nt < 8; nt++)
                #pragma unroll
                for (int r = 0; r < 4; r++) sacc[nt][r] = 0.f;

            #pragma unroll
            for (int ks = 0; ks < 4; ks++) {
                uint32_t qh[4], ql[4];
                {
                    uint32_t off = (uint32_t)((wid * 16 + (g8 & 1) * 8 + r8) * SKB
                                              + (ks * 16 + (g8 >> 1) * 8) * 2);
                    LDMX4(qh[0], qh[1], qh[2], qh[3], sQh + off);
                    LDMX4(ql[0], ql[1], ql[2], ql[3], sQl + off);
                }
                #pragma unroll
                for (int np = 0; np < 4; np++) {
                    uint32_t off = (uint32_t)((np * 16 + (g8 >> 1) * 8 + r8) * SKB
                                              + (ks * 16 + (g8 & 1) * 8) * 2);
                    uint32_t kh0, kh1, kh2, kh3, kl0, kl1, kl2, kl3;
                    LDMX4(kh0, kh1, kh2, kh3, sKh + off);
                    LDMX4(kl0, kl1, kl2, kl3, sKl + off);
                    mma16816(sacc[2 * np],     qh, kh0, kh1);
                    mma16816(sacc[2 * np],     qh, kl0, kl1);
                    mma16816(sacc[2 * np],     ql, kh0, kh1);
                    mma16816(sacc[2 * np + 1], qh, kh2, kh3);
                    mma16816(sacc[2 * np + 1], qh, kl2, kl3);
                    mma16816(sacc[2 * np + 1], ql, kh2, kh3);
                }
            }

            // ---- causal mask (only truly-partial warp/tile pairs) ----
            const bool need_mask = (kt == 2 * qt && wid < 4) ||
                                   (kt == last   && wid >= 4);
            if (need_mask) {
                const int r0 = q0 + wid * 16 + lg;
                const int kb = kt * 64;
                #pragma unroll
                for (int nt = 0; nt < 8; nt++) {
                    int j0 = kb + nt * 8 + lk, j1 = j0 + 1;
                    if (j0 > r0)     sacc[nt][0] = -1e30f;
                    if (j1 > r0)     sacc[nt][1] = -1e30f;
                    if (j0 > r0 + 8) sacc[nt][2] = -1e30f;
                    if (j1 > r0 + 8) sacc[nt][3] = -1e30f;
                }
            }

            // ---- online softmax ----
            float corr[2];
            #pragma unroll
            for (int hrow = 0; hrow < 2; hrow++) {
                float rm = -1e30f;
                #pragma unroll
                for (int nt = 0; nt < 8; nt++)
                    rm = fmaxf(rm, fmaxf(sacc[nt][2 * hrow], sacc[nt][2 * hrow + 1]));
                rm = fmaxf(rm, __shfl_xor_sync(0xffffffffu, rm, 1));
                rm = fmaxf(rm, __shfl_xor_sync(0xffffffffu, rm, 2));
                float mn = fmaxf(m[hrow], rm);
                corr[hrow] = __expf(m[hrow] - mn);
                m[hrow] = mn;
                float rs = 0.f;
                #pragma unroll
                for (int nt = 0; nt < 8; nt++) {
                    float p0 = __expf(sacc[nt][2 * hrow]     - mn);
                    float p1 = __expf(sacc[nt][2 * hrow + 1] - mn);
                    sacc[nt][2 * hrow] = p0; sacc[nt][2 * hrow + 1] = p1;
                    rs += p0 + p1;
                }
                rs += __shfl_xor_sync(0xffffffffu, rs, 1);
                rs += __shfl_xor_sync(0xffffffffu, rs, 2);
                l[hrow] = l[hrow] * corr[hrow] + rs;
            }
            #pragma unroll
            for (int nt = 0; nt < 8; nt++) {
                oacc[nt][0] *= corr[0]; oacc[nt][1] *= corr[0];
                oacc[nt][2] *= corr[1]; oacc[nt][3] *= corr[1];
            }

            // ---- O += P @ V (split; P fragments built in-register) ----
            #pragma unroll
            for (int ks2 = 0; ks2 < 4; ks2++) {
                uint32_t pah[4], pal[4];
                #pragma unroll
                for (int hf = 0; hf < 2; hf++) {
                    const float* c = sacc[2 * ks2 + hf];
                    __nv_bfloat162 h0 = __floats2bfloat162_rn(c[0], c[1]);
                    __nv_bfloat162 h1 = __floats2bfloat162_rn(c[2], c[3]);
                    pah[2 * hf]     = *(uint32_t*)&h0;
                    pah[2 * hf + 1] = *(uint32_t*)&h1;
                    __nv_bfloat162 l0 = __floats2bfloat162_rn(
                        c[0] - __bfloat162float(h0.x), c[1] - __bfloat162float(h0.y));
                    __nv_bfloat162 l1 = __floats2bfloat162_rn(
                        c[2] - __bfloat162float(h1.x), c[3] - __bfloat162float(h1.y));
                    pal[2 * hf]     = *(uint32_t*)&l0;
                    pal[2 * hf + 1] = *(uint32_t*)&l1;
                }
                #pragma unroll
                for (int nd = 0; nd < 4; nd++) {
                    uint32_t off = (uint32_t)((ks2 * 16 + (g8 & 1) * 8 + r8) * SKB
                                              + (nd * 16 + (g8 >> 1) * 8) * 2);
                    uint32_t vh0, vh1, vh2, vh3, vl0, vl1, vl2, vl3;
                    LDMX4T(vh0, vh1, vh2, vh3, sVh + off);
                    LDMX4T(vl0, vl1, vl2, vl3, sVl + off);
                    mma16816(oacc[2 * nd],     pah, vh0, vh1);
                    mma16816(oacc[2 * nd],     pah, vl0, vl1);
                    mma16816(oacc[2 * nd],     pal, vh0, vh1);
                    mma16816(oacc[2 * nd + 1], pah, vh2, vh3);
                    mma16816(oacc[2 * nd + 1], pah, vl2, vl3);
                    mma16816(oacc[2 * nd + 1], pal, vh2, vh3);
                }
            }
        }
        __syncthreads();
    }

    // ---- epilogue ----
    const float inv0 = 1.f / l[0], inv1 = 1.f / l[1];
    const int row0 = q0 + wid * 16 + lg;
    #pragma unroll
    for (int nt = 0; nt < 8; nt++) {
        int col = nt * 8 + lk;
        float v0 = oacc[nt][0] * inv0, v1 = oacc[nt][1] * inv0;
        __nv_bfloat162 h0 = __floats2bfloat162_rn(v0, v1);
        __nv_bfloat162 l0 = __floats2bfloat162_rn(
            v0 - __bfloat162float(h0.x), v1 - __bfloat162float(h0.y));
        *(__nv_bfloat162*)&AOh[gbase + (size_t)row0 * D_MODEL + col] = h0;
        *(__nv_bfloat162*)&AOl[gbase + (size_t)row0 * D_MODEL + col] = l0;
        float v2 = oacc[nt][2] * inv1, v3 = oacc[nt][3] * inv1;
        __nv_bfloat162 h1 = __floats2bfloat162_rn(v2, v3);
        __nv_bfloat162 l1 = __floats2bfloat162_rn(
            v2 - __bfloat162float(h1.x), v3 - __bfloat162float(h1.y));
        *(__nv_bfloat162*)&AOh[gbase + (size_t)(row0 + 8) * D_MODEL + col] = h1;
        *(__nv_bfloat162*)&AOl[gbase + (size_t)(row0 + 8) * D_MODEL + col] = l1;
    }
}

// ---------------------------------------------------------------------------
// Launch — 5 kernels total
// ---------------------------------------------------------------------------
extern "C" void kernel_launch(void* const* d_in, const int* in_sizes, int n_in,
                              void* d_out, int out_size)
{
    const float* q  = (const float*)d_in[0];
    const float* k  = (const float*)d_in[1];
    const float* v  = (const float*)d_in[2];
    const float* wq = (const float*)d_in[3];
    const float* bq = (const float*)d_in[4];
    const float* wk = (const float*)d_in[5];
    const float* bk = (const float*)d_in[6];
    const float* wv = (const float*)d_in[7];
    const float* bv = (const float*)d_in[8];
    const float* wo = (const float*)d_in[9];
    const float* bo = (const float*)d_in[10];
    float* out = (float*)d_out;

    __nv_bfloat16 *sph, *spl, *wh, *wl, *qkvh, *qkvl, *aoh, *aol;
    cudaGetSymbolAddress((void**)&sph,  g_sph);  cudaGetSymbolAddress((void**)&spl,  g_spl);
    cudaGetSymbolAddress((void**)&wh,   g_wh);   cudaGetSymbolAddress((void**)&wl,   g_wl);
    cudaGetSymbolAddress((void**)&qkvh, g_qkvh); cudaGetSymbolAddress((void**)&qkvl, g_qkvl);
    cudaGetSymbolAddress((void**)&aoh,  g_aoh);  cudaGetSymbolAddress((void**)&aol,  g_aol);

    cudaFuncSetAttribute(gemm_mma<true>,
                         cudaFuncAttributeMaxDynamicSharedMemorySize, GSMEM);
    cudaFuncSetAttribute(gemm_mma<false>,
                         cudaFuncAttributeMaxDynamicSharedMemorySize, GSMEM);
    cudaFuncSetAttribute(attn_mma,
                         cudaFuncAttributeMaxDynamicSharedMemorySize, ASMEM);

    // 1) transpose+split all 4 weights
    dim3 tgrid(D_MODEL / 32, D_MODEL / 32, 4), tblk(32, 8);
    split_t4_kernel<<<tgrid, tblk>>>(wq, wk, wv, wo, wh, wl);

    // 2) split q,k,v inputs
    dim3 sgrid(NELEMS / 4 / 256, 3);
    split3_kernel<<<sgrid, 256>>>(q, k, v, sph, spl);

    // 3) batched QKV projection
    dim3 ggrid(D_MODEL / 128, ROWS / 128, 3);   // (8, 32, 3)
    gemm_mma<true><<<ggrid, 256, GSMEM>>>(sph, spl, wh, wl, bq, bk, bv,
                                          nullptr, qkvh, qkvl);

    // 4) attention
    dim3 agrid(SEQ / 128, N_HEADS, BATCH);      // (16, 16, 2)
    attn_mma<<<agrid, 256, ASMEM>>>(qkvh, qkvl, aoh, aol);

    // 5) output projection (weight slab 3 = wo)
    dim3 ogrid(D_MODEL / 128, ROWS / 128, 1);
    gemm_mma<false><<<ogrid, 256, GSMEM>>>(aoh, aol, wh + 3 * (size_t)DD,
                                           wl + 3 * (size_t)DD, bo, bo, bo,
                                           out, nullptr, nullptr);
}

// round 15
// speedup vs baseline: 1.0408x; 1.0408x over previous
#include <cuda_runtime.h>
#include <cuda_bf16.h>
#include <cstdint>

#define D_MODEL 1024
#define N_HEADS 16
#define DEPTH   64
#define BATCH   2
#define SEQ     2048
#define ROWS    (BATCH*SEQ)
#define NELEMS  (ROWS*D_MODEL)
#define DD      (D_MODEL*D_MODEL)

// ---------------- scratch (device globals; no allocations) ----------------
__device__ __nv_bfloat16 g_sph [3 * NELEMS];   // split inputs (q,k,v) hi
__device__ __nv_bfloat16 g_spl [3 * NELEMS];   // split inputs lo
__device__ __nv_bfloat16 g_wh  [4 * DD];       // weights^T hi (wq,wk,wv,wo)
__device__ __nv_bfloat16 g_wl  [4 * DD];       // weights^T lo
__device__ __nv_bfloat16 g_qkvh[3 * NELEMS];   // projected Q,K,V hi
__device__ __nv_bfloat16 g_qkvl[3 * NELEMS];   // projected Q,K,V lo
__device__ __nv_bfloat16 g_aoh [NELEMS];       // attention out hi
__device__ __nv_bfloat16 g_aol [NELEMS];       // attention out lo

// ---------------- helpers ----------------
__device__ __forceinline__ uint32_t smem_u32(const void* p) {
    uint32_t a;
    asm("{ .reg .u64 t; cvta.to.shared.u64 t, %1; cvt.u32.u64 %0, t; }"
        : "=r"(a) : "l"(p));
    return a;
}
__device__ __forceinline__ void mma16816(float* d, const uint32_t* a,
                                         uint32_t b0, uint32_t b1) {
    asm volatile(
        "mma.sync.aligned.m16n8k16.row.col.f32.bf16.bf16.f32 "
        "{%0,%1,%2,%3}, {%4,%5,%6,%7}, {%8,%9}, {%0,%1,%2,%3};"
        : "+f"(d[0]), "+f"(d[1]), "+f"(d[2]), "+f"(d[3])
        : "r"(a[0]), "r"(a[1]), "r"(a[2]), "r"(a[3]), "r"(b0), "r"(b1));
}
#define LDMX4(r0, r1, r2, r3, addr) \
    asm volatile("ldmatrix.sync.aligned.m8n8.x4.shared.b16 {%0,%1,%2,%3}, [%4];" \
                 : "=r"(r0), "=r"(r1), "=r"(r2), "=r"(r3) : "r"(addr))
#define LDMX4T(r0, r1, r2, r3, addr) \
    asm volatile("ldmatrix.sync.aligned.m8n8.x4.trans.shared.b16 {%0,%1,%2,%3}, [%4];" \
                 : "=r"(r0), "=r"(r1), "=r"(r2), "=r"(r3) : "r"(addr))
#define CPASYNC16(smaddr, gptr) \
    asm volatile("cp.async.cg.shared.global [%0], [%1], 16;" \
                 :: "r"(smaddr), "l"(gptr) : "memory")
#define CPCOMMIT()  asm volatile("cp.async.commit_group;" ::: "memory")
#define CPWAIT(n)   asm volatile("cp.async.wait_group %0;" :: "n"(n) : "memory")

// ---------------------------------------------------------------------------
// Batched split: fp32 -> (bf16 hi, bf16 lo).  blockIdx.y selects input 0..2.
// ---------------------------------------------------------------------------
__global__ __launch_bounds__(256) void split3_kernel(
    const float* __restrict__ in0, const float* __restrict__ in1,
    const float* __restrict__ in2,
    __nv_bfloat16* __restrict__ hi, __nv_bfloat16* __restrict__ lo)
{
    const int z = blockIdx.y;
    const float* in = (z == 0) ? in0 : (z == 1) ? in1 : in2;
    int i = (blockIdx.x * 256 + threadIdx.x) * 4;
    if (i >= NELEMS) return;
    float4 v = *(const float4*)(in + i);
    union { __nv_bfloat16 b[4]; uint2 u; } H, L;
    float f[4] = {v.x, v.y, v.z, v.w};
    #pragma unroll
    for (int j = 0; j < 4; j++) {
        H.b[j] = __float2bfloat16_rn(f[j]);
        L.b[j] = __float2bfloat16_rn(f[j] - __bfloat162float(H.b[j]));
    }
    size_t o = (size_t)z * NELEMS + i;
    *(uint2*)(hi + o) = H.u;
    *(uint2*)(lo + o) = L.u;
}

// ---------------------------------------------------------------------------
// Batched transpose+split: W[K][N] fp32 -> Wt hi/lo [N][K] bf16. z = 0..3.
// ---------------------------------------------------------------------------
__global__ __launch_bounds__(256) void split_t4_kernel(
    const float* __restrict__ W0, const float* __restrict__ W1,
    const float* __restrict__ W2, const float* __restrict__ W3,
    __nv_bfloat16* __restrict__ th, __nv_bfloat16* __restrict__ tl)
{
    __shared__ float tile[32][33];
    const int z = blockIdx.z;
    const float* W = (z == 0) ? W0 : (z == 1) ? W1 : (z == 2) ? W2 : W3;
    const size_t zoff = (size_t)z * DD;
    int x  = blockIdx.x * 32 + threadIdx.x;
    int y0 = blockIdx.y * 32;
    #pragma unroll
    for (int i = 0; i < 32; i += 8)
        tile[threadIdx.y + i][threadIdx.x] = W[(size_t)(y0 + threadIdx.y + i) * D_MODEL + x];
    __syncthreads();
    int k = y0 + threadIdx.x;
    #pragma unroll
    for (int i = 0; i < 32; i += 8) {
        int nn = blockIdx.x * 32 + threadIdx.y + i;
        float v = tile[threadIdx.x][threadIdx.y + i];
        __nv_bfloat16 h = __float2bfloat16_rn(v);
        th[zoff + (size_t)nn * D_MODEL + k] = h;
        tl[zoff + (size_t)nn * D_MODEL + k] = __float2bfloat16_rn(v - __bfloat162float(h));
    }
}

// ---------------------------------------------------------------------------
// bf16x2-split GEMM (proven core), batched over blockIdx.z.
// ---------------------------------------------------------------------------
#define SA 40
#define MATB   (128 * SA * 2)
#define STAGEB (4 * MATB)
#define GSMEM  (2 * STAGEB)

template<bool SPLIT_OUT>
__global__ __launch_bounds__(256, 2) void gemm_mma(
    const __nv_bfloat16* __restrict__ Ah0, const __nv_bfloat16* __restrict__ Al0,
    const __nv_bfloat16* __restrict__ Bh0, const __nv_bfloat16* __restrict__ Bl0,
    const float* __restrict__ b0, const float* __restrict__ b1,
    const float* __restrict__ b2,
    float* __restrict__ Cf,
    __nv_bfloat16* __restrict__ Ch0, __nv_bfloat16* __restrict__ Cl0)
{
    extern __shared__ char smem[];
    const uint32_t sb = smem_u32(smem);

    const int z = blockIdx.z;
    const __nv_bfloat16* Ah = Ah0 + (size_t)z * NELEMS;
    const __nv_bfloat16* Al = Al0 + (size_t)z * NELEMS;
    const __nv_bfloat16* Bh = Bh0 + (size_t)z * DD;
    const __nv_bfloat16* Bl = Bl0 + (size_t)z * DD;
    const float* bias = (z == 0) ? b0 : (z == 1) ? b1 : b2;
    __nv_bfloat16* Ch = Ch0 + (size_t)z * NELEMS;
    __nv_bfloat16* Cl = Cl0 + (size_t)z * NELEMS;

    const int tid  = threadIdx.x;
    const int wid  = tid >> 5, lane = tid & 31;
    const int wm   = wid & 3;
    const int wn   = wid >> 2;
    const int m0   = blockIdx.y * 128, n0 = blockIdx.x * 128;
    const int lg   = lane >> 2;
    const int lk   = (lane & 3) * 2;
    const int g8 = lane >> 3;
    const int r8 = lane & 7;

    float acc[2][8][4];
    #pragma unroll
    for (int mt = 0; mt < 2; mt++)
        #pragma unroll
        for (int nt = 0; nt < 8; nt++)
            #pragma unroll
            for (int r = 0; r < 4; r++) acc[mt][nt][r] = 0.f;

    auto load_stage = [&](int st, int k0) {
        const uint32_t s = sb + st * STAGEB;
        #pragma unroll
        for (int i = 0; i < 2; i++) {
            int idx = tid + i * 256;
            int r   = idx >> 2;
            int c16 = idx & 3;
            uint32_t so = (uint32_t)(r * (SA * 2) + c16 * 16);
            size_t ga = (size_t)(m0 + r) * D_MODEL + k0 + c16 * 8;
            size_t gb = (size_t)(n0 + r) * D_MODEL + k0 + c16 * 8;
            CPASYNC16(s + 0 * MATB + so, Ah + ga);
            CPASYNC16(s + 1 * MATB + so, Al + ga);
            CPASYNC16(s + 2 * MATB + so, Bh + gb);
            CPASYNC16(s + 3 * MATB + so, Bl + gb);
        }
    };

    load_stage(0, 0);
    CPCOMMIT();

    const int NIT = D_MODEL / 32;
    for (int it = 0; it < NIT; it++) {
        if (it + 1 < NIT) {
            load_stage((it + 1) & 1, (it + 1) * 32);
            CPCOMMIT();
            CPWAIT(1);
        } else {
            CPWAIT(0);
        }
        __syncthreads();

        const uint32_t s   = sb + (it & 1) * STAGEB;
        const uint32_t sAh = s;
        const uint32_t sAl = s + MATB;
        const uint32_t sBh = s + 2 * MATB;
        const uint32_t sBl = s + 3 * MATB;

        #pragma unroll
        for (int kk = 0; kk < 32; kk += 16) {
            uint32_t ah[2][4], al[2][4];
            #pragma unroll
            for (int mt = 0; mt < 2; mt++) {
                int row = wm * 32 + mt * 16 + (g8 & 1) * 8 + r8;
                int col = kk + (g8 >> 1) * 8;
                uint32_t off = (uint32_t)(row * (SA * 2) + col * 2);
                LDMX4(ah[mt][0], ah[mt][1], ah[mt][2], ah[mt][3], sAh + off);
                LDMX4(al[mt][0], al[mt][1], al[mt][2], al[mt][3], sAl + off);
            }
            #pragma unroll
            for (int np = 0; np < 4; np++) {
                int row = wn * 64 + np * 16 + (g8 >> 1) * 8 + r8;
                int col = kk + (g8 & 1) * 8;
                uint32_t off = (uint32_t)(row * (SA * 2) + col * 2);
                uint32_t bh0, bh1, bh2, bh3, bl0, bl1, bl2, bl3;
                LDMX4(bh0, bh1, bh2, bh3, sBh + off);
                LDMX4(bl0, bl1, bl2, bl3, sBl + off);
                #pragma unroll
                for (int mt = 0; mt < 2; mt++) {
                    mma16816(acc[mt][2 * np],     ah[mt], bh0, bh1);
                    mma16816(acc[mt][2 * np],     ah[mt], bl0, bl1);
                    mma16816(acc[mt][2 * np],     al[mt], bh0, bh1);
                    mma16816(acc[mt][2 * np + 1], ah[mt], bh2, bh3);
                    mma16816(acc[mt][2 * np + 1], ah[mt], bl2, bl3);
                    mma16816(acc[mt][2 * np + 1], al[mt], bh2, bh3);
                }
            }
        }
        __syncthreads();
    }

    #pragma unroll
    for (int mt = 0; mt < 2; mt++) {
        #pragma unroll
        for (int nt = 0; nt < 8; nt++) {
            int row = m0 + wm * 32 + mt * 16 + lg;
            int col = n0 + wn * 64 + nt * 8 + lk;
            float2 bb = *(const float2*)&bias[col];
            float v00 = acc[mt][nt][0] + bb.x, v01 = acc[mt][nt][1] + bb.y;
            float v10 = acc[mt][nt][2] + bb.x, v11 = acc[mt][nt][3] + bb.y;
            if (SPLIT_OUT) {
                __nv_bfloat162 h0 = __floats2bfloat162_rn(v00, v01);
                __nv_bfloat162 l0 = __floats2bfloat162_rn(
                    v00 - __bfloat162float(h0.x), v01 - __bfloat162float(h0.y));
                __nv_bfloat162 h1 = __floats2bfloat162_rn(v10, v11);
                __nv_bfloat162 l1 = __floats2bfloat162_rn(
                    v10 - __bfloat162float(h1.x), v11 - __bfloat162float(h1.y));
                *(__nv_bfloat162*)&Ch[(size_t)row * D_MODEL + col] = h0;
                *(__nv_bfloat162*)&Cl[(size_t)row * D_MODEL + col] = l0;
                *(__nv_bfloat162*)&Ch[(size_t)(row + 8) * D_MODEL + col] = h1;
                *(__nv_bfloat162*)&Cl[(size_t)(row + 8) * D_MODEL + col] = l1;
            } else {
                float2 o0 = {v00, v01}, o1 = {v10, v11};
                *(float2*)&Cf[(size_t)row * D_MODEL + col] = o0;
                *(float2*)&Cf[(size_t)(row + 8) * D_MODEL + col] = o1;
            }
        }
    }
}

// ---------------------------------------------------------------------------
// Flash-attention via mma.sync bf16 split precision (causal, UNSCALED).
// 128-key KV stages (two 64-key halves); register-resident Q fragments;
// deferred l-reduction; fully-masked diagonal half skipped for warps 0-3.
// ---------------------------------------------------------------------------
#define SK   72
#define SKB  (SK * 2)                    // 144 B row stride
#define AQ_BYTES  (128 * SKB)            // 18432 per Q matrix
#define AKV_MAT   (128 * SKB)            // 18432 per K/V matrix (128 keys)
#define AKV_STAGE (4 * AKV_MAT)          // 73728
#define ASMEM (2 * AQ_BYTES + 2 * AKV_STAGE)   // 184320

__global__ __launch_bounds__(256, 1) void attn_mma(
    const __nv_bfloat16* __restrict__ qkvh, const __nv_bfloat16* __restrict__ qkvl,
    __nv_bfloat16* __restrict__ AOh, __nv_bfloat16* __restrict__ AOl)
{
    extern __shared__ char smem[];
    const uint32_t sb = smem_u32(smem);
    const uint32_t sQh = sb, sQl = sb + AQ_BYTES;
    const uint32_t sKV = sb + 2 * AQ_BYTES;

    const __nv_bfloat16* Qh = qkvh;
    const __nv_bfloat16* Ql = qkvl;
    const __nv_bfloat16* Kh = qkvh + (size_t)NELEMS;
    const __nv_bfloat16* Kl = qkvl + (size_t)NELEMS;
    const __nv_bfloat16* Vh = qkvh + 2 * (size_t)NELEMS;
    const __nv_bfloat16* Vl = qkvl + 2 * (size_t)NELEMS;

    const int qt = (gridDim.x - 1) - blockIdx.x;   // long CTAs first
    const int h  = blockIdx.y;
    const int b  = blockIdx.z;
    const int tid = threadIdx.x;
    const int wid = tid >> 5, lane = tid & 31;
    const int lg = lane >> 2, lk = (lane & 3) * 2;
    const int g8 = lane >> 3, r8 = lane & 7;

    const int q0 = qt * 128;
    const size_t gbase = ((size_t)b * SEQ) * D_MODEL + h * DEPTH;

    // ---- Q loads (hi+lo) ----
    #pragma unroll
    for (int i = 0; i < 4; i++) {
        int idx = tid + i * 256;
        int r = idx >> 3, c = idx & 7;
        uint32_t so = (uint32_t)(r * SKB + c * 16);
        size_t g = gbase + (size_t)(q0 + r) * D_MODEL + c * 8;
        CPASYNC16(sQh + so, Qh + g);
        CPASYNC16(sQl + so, Ql + g);
    }

    // 128-key stage loader: 4 arrays x 128 rows x 128B = 64KB
    auto load_kv = [&](int st, int t) {
        const uint32_t s = sKV + st * AKV_STAGE;
        const int k0 = t * 128;
        #pragma unroll
        for (int i = 0; i < 16; i++) {
            int idx = tid + i * 256;          // 0..4095
            int arr = idx >> 10;              // 0..3
            int r = (idx >> 3) & 127, c = idx & 7;
            uint32_t so = s + arr * AKV_MAT + (uint32_t)(r * SKB + c * 16);
            size_t g = gbase + (size_t)(k0 + r) * D_MODEL + c * 8;
            const __nv_bfloat16* src = (arr == 0) ? Kh : (arr == 1) ? Kl
                                      : (arr == 2) ? Vh : Vl;
            CPASYNC16(so, src + g);
        }
    };

    load_kv(0, 0);
    CPCOMMIT();

    float m[2] = {-1e30f, -1e30f}, l[2] = {0.f, 0.f};   // l: quad-partial
    float oacc[8][4];
    #pragma unroll
    for (int nt = 0; nt < 8; nt++)
        #pragma unroll
        for (int r = 0; r < 4; r++) oacc[nt][r] = 0.f;

    uint32_t qfh[4][4], qfl[4][4];
    bool qloaded = false;

    for (int t = 0; t <= qt; t++) {
        if (t < qt) {
            load_kv((t + 1) & 1, t + 1);
            CPCOMMIT();
            CPWAIT(1);
        } else {
            CPWAIT(0);
        }
        __syncthreads();

        if (!qloaded) {   // Q frags once (register-resident)
            qloaded = true;
            #pragma unroll
            for (int ks = 0; ks < 4; ks++) {
                uint32_t off = (uint32_t)((wid * 16 + (g8 & 1) * 8 + r8) * SKB
                                          + (ks * 16 + (g8 >> 1) * 8) * 2);
                LDMX4(qfh[ks][0], qfh[ks][1], qfh[ks][2], qfh[ks][3], sQh + off);
                LDMX4(qfl[ks][0], qfl[ks][1], qfl[ks][2], qfl[ks][3], sQl + off);
            }
        }

        const uint32_t sg = sKV + (t & 1) * AKV_STAGE;

        #pragma unroll
        for (int half = 0; half < 2; half++) {
            // Fully-masked (above diagonal) for warps 0-3 on half 1 of t==qt
            if (t == qt && half == 1 && wid < 4) continue;

            const uint32_t hoff = (uint32_t)(half * 64 * SKB);
            const uint32_t sKh = sg + hoff;
            const uint32_t sKl = sg + AKV_MAT + hoff;
            const uint32_t sVh = sg + 2 * AKV_MAT + hoff;
            const uint32_t sVl = sg + 3 * AKV_MAT + hoff;
            const int kb = t * 128 + half * 64;

            // ---- S = Q @ K^T (split) ----
            float sacc[8][4];
            #pragma unroll
            for (int nt = 0; nt < 8; nt++)
                #pragma unroll
                for (int r = 0; r < 4; r++) sacc[nt][r] = 0.f;

            #pragma unroll
            for (int ks = 0; ks < 4; ks++) {
                #pragma unroll
                for (int np = 0; np < 4; np++) {
                    uint32_t off = (uint32_t)((np * 16 + (g8 >> 1) * 8 + r8) * SKB
                                              + (ks * 16 + (g8 & 1) * 8) * 2);
                    uint32_t kh0, kh1, kh2, kh3, kl0, kl1, kl2, kl3;
                    LDMX4(kh0, kh1, kh2, kh3, sKh + off);
                    LDMX4(kl0, kl1, kl2, kl3, sKl + off);
                    mma16816(sacc[2 * np],     qfh[ks], kh0, kh1);
                    mma16816(sacc[2 * np],     qfh[ks], kl0, kl1);
                    mma16816(sacc[2 * np],     qfl[ks], kh0, kh1);
                    mma16816(sacc[2 * np + 1], qfh[ks], kh2, kh3);
                    mma16816(sacc[2 * np + 1], qfh[ks], kl2, kl3);
                    mma16816(sacc[2 * np + 1], qfl[ks], kh2, kh3);
                }
            }

            // ---- causal mask (only truly-partial warp/half pairs) ----
            const bool need_mask = (t == qt) &&
                ((half == 0 && wid < 4) || (half == 1 && wid >= 4));
            if (need_mask) {
                const int r0 = q0 + wid * 16 + lg;
                #pragma unroll
                for (int nt = 0; nt < 8; nt++) {
                    int j0 = kb + nt * 8 + lk, j1 = j0 + 1;
                    if (j0 > r0)     sacc[nt][0] = -1e30f;
                    if (j1 > r0)     sacc[nt][1] = -1e30f;
                    if (j0 > r0 + 8) sacc[nt][2] = -1e30f;
                    if (j1 > r0 + 8) sacc[nt][3] = -1e30f;
                }
            }

            // ---- online softmax (max quad-reduced; l kept quad-partial) ----
            float corr[2];
            #pragma unroll
            for (int hrow = 0; hrow < 2; hrow++) {
                float rm = -1e30f;
                #pragma unroll
                for (int nt = 0; nt < 8; nt++)
                    rm = fmaxf(rm, fmaxf(sacc[nt][2 * hrow], sacc[nt][2 * hrow + 1]));
                rm = fmaxf(rm, __shfl_xor_sync(0xffffffffu, rm, 1));
                rm = fmaxf(rm, __shfl_xor_sync(0xffffffffu, rm, 2));
                float mn = fmaxf(m[hrow], rm);
                corr[hrow] = __expf(m[hrow] - mn);
                m[hrow] = mn;
                float rs = 0.f;
                #pragma unroll
                for (int nt = 0; nt < 8; nt++) {
                    float p0 = __expf(sacc[nt][2 * hrow]     - mn);
                    float p1 = __expf(sacc[nt][2 * hrow + 1] - mn);
                    sacc[nt][2 * hrow] = p0; sacc[nt][2 * hrow + 1] = p1;
                    rs += p0 + p1;
                }
                l[hrow] = l[hrow] * corr[hrow] + rs;   // quad-partial (deferred)
            }
            #pragma unroll
            for (int nt = 0; nt < 8; nt++) {
                oacc[nt][0] *= corr[0]; oacc[nt][1] *= corr[0];
                oacc[nt][2] *= corr[1]; oacc[nt][3] *= corr[1];
            }

            // ---- O += P @ V (split; P fragments built in-register) ----
            #pragma unroll
            for (int ks2 = 0; ks2 < 4; ks2++) {
                uint32_t pah[4], pal[4];
                #pragma unroll
                for (int hf = 0; hf < 2; hf++) {
                    const float* c = sacc[2 * ks2 + hf];
                    __nv_bfloat162 h0 = __floats2bfloat162_rn(c[0], c[1]);
                    __nv_bfloat162 h1 = __floats2bfloat162_rn(c[2], c[3]);
                    pah[2 * hf]     = *(uint32_t*)&h0;
                    pah[2 * hf + 1] = *(uint32_t*)&h1;
                    __nv_bfloat162 l0 = __floats2bfloat162_rn(
                        c[0] - __bfloat162float(h0.x), c[1] - __bfloat162float(h0.y));
                    __nv_bfloat162 l1 = __floats2bfloat162_rn(
                        c[2] - __bfloat162float(h1.x), c[3] - __bfloat162float(h1.y));
                    pal[2 * hf]     = *(uint32_t*)&l0;
                    pal[2 * hf + 1] = *(uint32_t*)&l1;
                }
                #pragma unroll
                for (int nd = 0; nd < 4; nd++) {
                    uint32_t off = (uint32_t)((ks2 * 16 + (g8 & 1) * 8 + r8) * SKB
                                              + (nd * 16 + (g8 >> 1) * 8) * 2);
                    uint32_t vh0, vh1, vh2, vh3, vl0, vl1, vl2, vl3;
                    LDMX4T(vh0, vh1, vh2, vh3, sVh + off);
                    LDMX4T(vl0, vl1, vl2, vl3, sVl + off);
                    mma16816(oacc[2 * nd],     pah, vh0, vh1);
                    mma16816(oacc[2 * nd],     pah, vl0, vl1);
                    mma16816(oacc[2 * nd],     pal, vh0, vh1);
                    mma16816(oacc[2 * nd + 1], pah, vh2, vh3);
                    mma16816(oacc[2 * nd + 1], pah, vl2, vl3);
                    mma16816(oacc[2 * nd + 1], pal, vh2, vh3);
                }
            }
        }
        __syncthreads();
    }

    // ---- deferred l quad-reduction ----
    #pragma unroll
    for (int hrow = 0; hrow < 2; hrow++) {
        l[hrow] += __shfl_xor_sync(0xffffffffu, l[hrow], 1);
        l[hrow] += __shfl_xor_sync(0xffffffffu, l[hrow], 2);
    }

    // ---- epilogue ----
    const float inv0 = 1.f / l[0], inv1 = 1.f / l[1];
    const int row0 = q0 + wid * 16 + lg;
    #pragma unroll
    for (int nt = 0; nt < 8; nt++) {
        int col = nt * 8 + lk;
        float v0 = oacc[nt][0] * inv0, v1 = oacc[nt][1] * inv0;
        __nv_bfloat162 h0 = __floats2bfloat162_rn(v0, v1);
        __nv_bfloat162 l0 = __floats2bfloat162_rn(
            v0 - __bfloat162float(h0.x), v1 - __bfloat162float(h0.y));
        *(__nv_bfloat162*)&AOh[gbase + (size_t)row0 * D_MODEL + col] = h0;
        *(__nv_bfloat162*)&AOl[gbase + (size_t)row0 * D_MODEL + col] = l0;
        float v2 = oacc[nt][2] * inv1, v3 = oacc[nt][3] * inv1;
        __nv_bfloat162 h1 = __floats2bfloat162_rn(v2, v3);
        __nv_bfloat162 l1 = __floats2bfloat162_rn(
            v2 - __bfloat162float(h1.x), v3 - __bfloat162float(h1.y));
        *(__nv_bfloat162*)&AOh[gbase + (size_t)(row0 + 8) * D_MODEL + col] = h1;
        *(__nv_bfloat162*)&AOl[gbase + (size_t)(row0 + 8) * D_MODEL + col] = l1;
    }
}

// ---------------------------------------------------------------------------
// Launch — 5 kernels total
// ---------------------------------------------------------------------------
extern "C" void kernel_launch(void* const* d_in, const int* in_sizes, int n_in,
                              void* d_out, int out_size)
{
    const float* q  = (const float*)d_in[0];
    const float* k  = (const float*)d_in[1];
    const float* v  = (const float*)d_in[2];
    const float* wq = (const float*)d_in[3];
    const float* bq = (const float*)d_in[4];
    const float* wk = (const float*)d_in[5];
    const float* bk = (const float*)d_in[6];
    const float* wv = (const float*)d_in[7];
    const float* bv = (const float*)d_in[8];
    const float* wo = (const float*)d_in[9];
    const float* bo = (const float*)d_in[10];
    float* out = (float*)d_out;

    __nv_bfloat16 *sph, *spl, *wh, *wl, *qkvh, *qkvl, *aoh, *aol;
    cudaGetSymbolAddress((void**)&sph,  g_sph);  cudaGetSymbolAddress((void**)&spl,  g_spl);
    cudaGetSymbolAddress((void**)&wh,   g_wh);   cudaGetSymbolAddress((void**)&wl,   g_wl);
    cudaGetSymbolAddress((void**)&qkvh, g_qkvh); cudaGetSymbolAddress((void**)&qkvl, g_qkvl);
    cudaGetSymbolAddress((void**)&aoh,  g_aoh);  cudaGetSymbolAddress((void**)&aol,  g_aol);

    cudaFuncSetAttribute(gemm_mma<true>,
                         cudaFuncAttributeMaxDynamicSharedMemorySize, GSMEM);
    cudaFuncSetAttribute(gemm_mma<false>,
                         cudaFuncAttributeMaxDynamicSharedMemorySize, GSMEM);
    cudaFuncSetAttribute(attn_mma,
                         cudaFuncAttributeMaxDynamicSharedMemorySize, ASMEM);

    // 1) transpose+split all 4 weights
    dim3 tgrid(D_MODEL / 32, D_MODEL / 32, 4), tblk(32, 8);
    split_t4_kernel<<<tgrid, tblk>>>(wq, wk, wv, wo, wh, wl);

    // 2) split q,k,v inputs
    dim3 sgrid(NELEMS / 4 / 256, 3);
    split3_kernel<<<sgrid, 256>>>(q, k, v, sph, spl);

    // 3) batched QKV projection
    dim3 ggrid(D_MODEL / 128, ROWS / 128, 3);   // (8, 32, 3)
    gemm_mma<true><<<ggrid, 256, GSMEM>>>(sph, spl, wh, wl, bq, bk, bv,
                                          nullptr, qkvh, qkvl);

    // 4) attention
    dim3 agrid(SEQ / 128, N_HEADS, BATCH);      // (16, 16, 2)
    attn_mma<<<agrid, 256, ASMEM>>>(qkvh, qkvl, aoh, aol);

    // 5) output projection (weight slab 3 = wo)
    dim3 ogrid(D_MODEL / 128, ROWS / 128, 1);
    gemm_mma<false><<<ogrid, 256, GSMEM>>>(aoh, aol, wh + 3 * (size_t)DD,
                                           wl + 3 * (size_t)DD, bo, bo, bo,
                                           out, nullptr, nullptr);
}